// round 10
// baseline (speedup 1.0000x reference)
#include <cuda_runtime.h>
#include <cstddef>

typedef unsigned long long ull;

// ---------------------------------------------------------------------------
// Packed f32x2 helpers (FFMA2 — only reachable via PTX)
// ---------------------------------------------------------------------------
__device__ __forceinline__ ull fma2(ull a, ull b, ull c) {
    ull d;
    asm("fma.rn.f32x2 %0, %1, %2, %3;" : "=l"(d) : "l"(a), "l"(b), "l"(c));
    return d;
}
__device__ __forceinline__ ull pack2(float x) {
    ull d;
    asm("mov.b64 %0, {%1, %1};" : "=l"(d) : "f"(x));
    return d;
}
__device__ __forceinline__ void unpack2(ull v, float& lo, float& hi) {
    asm("mov.b64 {%0, %1}, %2;" : "=f"(lo), "=f"(hi) : "l"(v));
}

// ---------------------------------------------------------------------------
// Scratch (device globals — no runtime allocation allowed)
// ---------------------------------------------------------------------------
__device__ float g_enc_b1[16 * 128 * 128 * 128];
__device__ float g_enc_b [16 * 128 * 64 * 64];
__device__ float g_enc_t [16 * 128 * 32 * 32];
__device__ float g_qt    [16 * 32 * 32 * 64];
__device__ float g_dec_t [16 * 64 * 64 * 64];
__device__ float g_qb    [16 * 64 * 64 * 64];
__device__ float g_up_t  [16 * 64 * 64 * 64];
__device__ float g_h     [16 * 64 * 128 * 128];
__device__ float g_e2t[512];
__device__ float g_e2b[512];
__device__ float g_sum_t[1];
__device__ float g_sum_b[1];

// ---------------------------------------------------------------------------
__global__ void prep_kernel(const float* __restrict__ et, const float* __restrict__ eb) {
    int t = blockIdx.x * blockDim.x + threadIdx.x;
    if (t < 512) {
        float s = 0.f;
        for (int d = 0; d < 64; ++d) { float v = et[d * 512 + t]; s = fmaf(v, v, s); }
        g_e2t[t] = s;
    } else if (t < 1024) {
        int k = t - 512;
        float s = 0.f;
        for (int d = 0; d < 64; ++d) { float v = eb[d * 512 + k]; s = fmaf(v, v, s); }
        g_e2b[k] = s;
    }
    if (t == 0) { g_sum_t[0] = 0.f; g_sum_b[0] = 0.f; }
}

// ---------------------------------------------------------------------------
// conv_down256: 4x4 s2 p1 downsample, NCHW. 256 thr = (16 tx, 16 ty), out
// tile 16 wide x 32 tall (rows ty, ty+16). Same inner body as R3 kernel.
// ---------------------------------------------------------------------------
template <int COG, int RELU>
__global__ void __launch_bounds__(256) conv_down256_k(
    const float* __restrict__ x, const float* __restrict__ w,
    const float* __restrict__ bias, float* __restrict__ y,
    int N, int Ci, int Hi, int Wi, int Co)
{
    const int Ho = Hi >> 1, Wo = Wi >> 1;
    __shared__ float sx[4][66][35];
    __shared__ __align__(16) float sw[16 * 4 * COG];

    const int tid = threadIdx.x;
    const int tx = tid & 15, ty = tid >> 4;
    const int cogs = Co / COG;
    const int n = blockIdx.z / cogs, cog = blockIdx.z % cogs;
    const int wo = blockIdx.x * 16 + tx;
    const int ho0 = blockIdx.y * 32 + ty;
    const int hi0 = blockIdx.y * 64 - 1, wi0 = blockIdx.x * 32 - 1;

    ull acc[2][COG / 2];
#pragma unroll
    for (int p = 0; p < 2; ++p)
#pragma unroll
        for (int j = 0; j < COG / 2; ++j) acc[p][j] = 0ULL;

    for (int ci0 = 0; ci0 < Ci; ci0 += 4) {
        __syncthreads();
        for (int idx = tid; idx < 4 * 66 * 34; idx += 256) {
            int c = idx / 2244, rem = idx % 2244;
            int r = rem / 34, cc = rem % 34;
            int ci = ci0 + c, hi = hi0 + r, wi = wi0 + cc;
            float v = 0.f;
            if (ci < Ci && hi >= 0 && hi < Hi && wi >= 0 && wi < Wi)
                v = x[((size_t)(n * Ci + ci) * Hi + hi) * Wi + wi];
            sx[c][r][cc] = v;
        }
        for (int idx = tid; idx < 16 * 4 * COG; idx += 256) {
            int k = idx / (4 * COG), rem = idx % (4 * COG);
            int c = rem / COG, co = rem % COG;
            int ci = ci0 + c;
            sw[idx] = (ci < Ci) ? w[((size_t)(cog * COG + co) * Ci + ci) * 16 + k] : 0.f;
        }
        __syncthreads();
#pragma unroll
        for (int c = 0; c < 4; ++c) {
#pragma unroll
            for (int k = 0; k < 16; ++k) {
                const int kh = k >> 2, kw = k & 3;
                float f0 = sx[c][2 * ty + kh][2 * tx + kw];
                float f1 = sx[c][2 * ty + 32 + kh][2 * tx + kw];
                ull xp0 = pack2(f0), xp1 = pack2(f1);
                const ulonglong2* wp = (const ulonglong2*)&sw[(k * 4 + c) * COG];
#pragma unroll
                for (int j = 0; j < COG / 4; ++j) {
                    ulonglong2 wv = wp[j];
                    acc[0][2 * j + 0] = fma2(xp0, wv.x, acc[0][2 * j + 0]);
                    acc[0][2 * j + 1] = fma2(xp0, wv.y, acc[0][2 * j + 1]);
                    acc[1][2 * j + 0] = fma2(xp1, wv.x, acc[1][2 * j + 0]);
                    acc[1][2 * j + 1] = fma2(xp1, wv.y, acc[1][2 * j + 1]);
                }
            }
        }
    }
#pragma unroll
    for (int p = 0; p < 2; ++p) {
        int ho = ho0 + p * 16;
#pragma unroll
        for (int j = 0; j < COG / 2; ++j) {
            float v0, v1;
            unpack2(acc[p][j], v0, v1);
            int cg0 = cog * COG + 2 * j;
            v0 += bias[cg0];
            v1 += bias[cg0 + 1];
            if (RELU) { v0 = fmaxf(v0, 0.f); v1 = fmaxf(v1, 0.f); }
            y[((size_t)(n * Co + cg0) * Ho + ho) * Wo + wo] = v0;
            y[((size_t)(n * Co + cg0 + 1) * Ho + ho) * Wo + wo] = v1;
        }
    }
}

// ---------------------------------------------------------------------------
// conv_down2 (R3 body, 128 thr) — kept for conv3
// ---------------------------------------------------------------------------
template <int COG, int RELU>
__global__ void __launch_bounds__(128) conv_down2_k(
    const float* __restrict__ x, const float* __restrict__ w,
    const float* __restrict__ bias, float* __restrict__ y,
    int N, int Ci, int Hi, int Wi, int Co)
{
    const int Ho = Hi >> 1, Wo = Wi >> 1;
    __shared__ float sx[4][34][35];
    __shared__ __align__(16) float sw[16 * 4 * COG];

    const int tid = threadIdx.x;
    const int tx = tid & 15, ty = tid >> 4;
    const int cogs = Co / COG;
    const int n = blockIdx.z / cogs, cog = blockIdx.z % cogs;
    const int wo = blockIdx.x * 16 + tx;
    const int ho0 = blockIdx.y * 16 + ty;
    const int hi0 = blockIdx.y * 32 - 1, wi0 = blockIdx.x * 32 - 1;

    ull acc[2][COG / 2];
#pragma unroll
    for (int p = 0; p < 2; ++p)
#pragma unroll
        for (int j = 0; j < COG / 2; ++j) acc[p][j] = 0ULL;

    for (int ci0 = 0; ci0 < Ci; ci0 += 4) {
        __syncthreads();
        for (int idx = tid; idx < 4 * 34 * 34; idx += 128) {
            int c = idx / 1156, rem = idx % 1156;
            int r = rem / 34, cc = rem % 34;
            int ci = ci0 + c, hi = hi0 + r, wi = wi0 + cc;
            float v = 0.f;
            if (ci < Ci && hi >= 0 && hi < Hi && wi >= 0 && wi < Wi)
                v = x[((size_t)(n * Ci + ci) * Hi + hi) * Wi + wi];
            sx[c][r][cc] = v;
        }
        for (int idx = tid; idx < 16 * 4 * COG; idx += 128) {
            int k = idx / (4 * COG), rem = idx % (4 * COG);
            int c = rem / COG, co = rem % COG;
            int ci = ci0 + c;
            sw[idx] = (ci < Ci) ? w[((size_t)(cog * COG + co) * Ci + ci) * 16 + k] : 0.f;
        }
        __syncthreads();
#pragma unroll
        for (int c = 0; c < 4; ++c) {
#pragma unroll
            for (int k = 0; k < 16; ++k) {
                const int kh = k >> 2, kw = k & 3;
                float f0 = sx[c][2 * ty + kh][2 * tx + kw];
                float f1 = sx[c][2 * ty + 16 + kh][2 * tx + kw];
                ull xp0 = pack2(f0), xp1 = pack2(f1);
                const ulonglong2* wp = (const ulonglong2*)&sw[(k * 4 + c) * COG];
#pragma unroll
                for (int j = 0; j < COG / 4; ++j) {
                    ulonglong2 wv = wp[j];
                    acc[0][2 * j + 0] = fma2(xp0, wv.x, acc[0][2 * j + 0]);
                    acc[0][2 * j + 1] = fma2(xp0, wv.y, acc[0][2 * j + 1]);
                    acc[1][2 * j + 0] = fma2(xp1, wv.x, acc[1][2 * j + 0]);
                    acc[1][2 * j + 1] = fma2(xp1, wv.y, acc[1][2 * j + 1]);
                }
            }
        }
    }
#pragma unroll
    for (int p = 0; p < 2; ++p) {
        int ho = ho0 + p * 8;
#pragma unroll
        for (int j = 0; j < COG / 2; ++j) {
            float v0, v1;
            unpack2(acc[p][j], v0, v1);
            int cg0 = cog * COG + 2 * j;
            v0 += bias[cg0];
            v1 += bias[cg0 + 1];
            if (RELU) { v0 = fmaxf(v0, 0.f); v1 = fmaxf(v1, 0.f); }
            y[((size_t)(n * Co + cg0) * Ho + ho) * Wo + wo] = v0;
            y[((size_t)(n * Co + cg0 + 1) * Ho + ho) * Wo + wo] = v1;
        }
    }
}

// ---------------------------------------------------------------------------
// 1x1 conv over (optionally) two concatenated inputs, output NHWC, Co = 64.
// ---------------------------------------------------------------------------
__global__ void __launch_bounds__(128) conv1x1_nhwc_k(
    const float* __restrict__ in1, const float* __restrict__ in2,
    const float* __restrict__ w, const float* __restrict__ bias,
    float* __restrict__ y, int Ci1, int Ci2, int HW)
{
    __shared__ __align__(16) float sw[192 * 64]; // [ci][co]
    const int Ci = Ci1 + Ci2;
    const int tid = threadIdx.x;
    for (int idx = tid; idx < Ci * 64; idx += 128) {
        int ci = idx >> 6, co = idx & 63;
        sw[idx] = w[(size_t)co * Ci + ci];
    }
    __syncthreads();

    const int p = blockIdx.x * 128 + tid;
    const int n = p / HW, hw = p % HW;

    ull acc[32];
#pragma unroll
    for (int j = 0; j < 32; ++j) acc[j] = 0ULL;

    {
        const float* a0 = in1 + (size_t)n * Ci1 * HW + hw;
        for (int ci = 0; ci < Ci1; ++ci) {
            ull xp0 = pack2(a0[(size_t)ci * HW]);
            const ulonglong2* wp = (const ulonglong2*)&sw[ci * 64];
#pragma unroll
            for (int j = 0; j < 16; ++j) {
                ulonglong2 wv = wp[j];
                acc[2 * j + 0] = fma2(xp0, wv.x, acc[2 * j + 0]);
                acc[2 * j + 1] = fma2(xp0, wv.y, acc[2 * j + 1]);
            }
        }
    }
    if (Ci2 > 0) {
        const float* a0 = in2 + (size_t)n * Ci2 * HW + hw;
        for (int ci = 0; ci < Ci2; ++ci) {
            ull xp0 = pack2(a0[(size_t)ci * HW]);
            const ulonglong2* wp = (const ulonglong2*)&sw[(Ci1 + ci) * 64];
#pragma unroll
            for (int j = 0; j < 16; ++j) {
                ulonglong2 wv = wp[j];
                acc[2 * j + 0] = fma2(xp0, wv.x, acc[2 * j + 0]);
                acc[2 * j + 1] = fma2(xp0, wv.y, acc[2 * j + 1]);
            }
        }
    }
    float4* out4 = (float4*)&y[(size_t)p * 64];
#pragma unroll
    for (int j4 = 0; j4 < 16; ++j4) {
        float a, b, c, d;
        unpack2(acc[2 * j4 + 0], a, b);
        unpack2(acc[2 * j4 + 1], c, d);
        out4[j4] = make_float4(a + bias[4 * j4 + 0], b + bias[4 * j4 + 1],
                               c + bias[4 * j4 + 2], d + bias[4 * j4 + 3]);
    }
}

// ---------------------------------------------------------------------------
// Vector quantize (R3 body)
// ---------------------------------------------------------------------------
__global__ void __launch_bounds__(128) quantize_k(
    const float* __restrict__ z, const float* __restrict__ embed,
    const float* __restrict__ e2, float* __restrict__ qout,
    float* __restrict__ idout, float* __restrict__ sumout, int HW)
{
    __shared__ __align__(16) float sz[16 * 68];
    __shared__ __align__(16) float se[64 * 128];
    __shared__ float se2[128];
    __shared__ float swred[4];

    const int tid = threadIdx.x;
    const int m0 = blockIdx.x * 16;

    for (int idx = tid; idx < 16 * 64; idx += 128) {
        int v = idx >> 6, d = idx & 63;
        sz[v * 68 + d] = z[(size_t)(m0 + v) * 64 + d];
    }
    __syncthreads();

    const int v = tid >> 3, g = tid & 7;

    float z2 = 0.f;
    for (int d = 0; d < 64; ++d) { float t = sz[v * 68 + d]; z2 = fmaf(t, t, z2); }

    float bestd = 3.4e38f;
    int bestk = 0;

    for (int kc = 0; kc < 512; kc += 128) {
        __syncthreads();
        for (int idx = tid; idx < 64 * 128; idx += 128)
            se[idx] = embed[(size_t)(idx >> 7) * 512 + kc + (idx & 127)];
        if (tid < 128) se2[tid] = e2[kc + tid];
        __syncthreads();

        ull dotp[8];
#pragma unroll
        for (int j = 0; j < 8; ++j) dotp[j] = 0ULL;
        for (int d = 0; d < 64; ++d) {
            ull zp = pack2(sz[v * 68 + d]);
            const ulonglong2* ep = (const ulonglong2*)&se[d * 128 + g * 16];
#pragma unroll
            for (int m = 0; m < 4; ++m) {
                ulonglong2 ev = ep[m];
                dotp[2 * m + 0] = fma2(zp, ev.x, dotp[2 * m + 0]);
                dotp[2 * m + 1] = fma2(zp, ev.y, dotp[2 * m + 1]);
            }
        }
#pragma unroll
        for (int m = 0; m < 8; ++m) {
            float d0, d1;
            unpack2(dotp[m], d0, d1);
            int j0 = 2 * m;
            float dist0 = (z2 - 2.f * d0) + se2[g * 16 + j0];
            float dist1 = (z2 - 2.f * d1) + se2[g * 16 + j0 + 1];
            int k0 = kc + g * 16 + j0;
            if (dist0 < bestd) { bestd = dist0; bestk = k0; }
            if (dist1 < bestd) { bestd = dist1; bestk = k0 + 1; }
        }
    }

#pragma unroll
    for (int off = 4; off; off >>= 1) {
        float od = __shfl_down_sync(0xffffffffu, bestd, off, 8);
        int   ok = __shfl_down_sync(0xffffffffu, bestk, off, 8);
        if (od < bestd || (od == bestd && ok < bestk)) { bestd = od; bestk = ok; }
    }
    bestk = __shfl_sync(0xffffffffu, bestk, 0, 8);

    const int m = m0 + v;
    const int n = m / HW, hw = m % HW;
    float lsum = 0.f;
    float* qbase = qout + (size_t)n * 64 * HW + hw;
#pragma unroll
    for (int dd = 0; dd < 8; ++dd) {
        int d = g * 8 + dd;
        float q = embed[(size_t)d * 512 + bestk];
        float zv = sz[v * 68 + d];
        float df = q - zv;
        lsum = fmaf(df, df, lsum);
        qbase[(size_t)d * HW] = zv + (q - zv);
    }
    if (g == 0) idout[m] = (float)bestk;

#pragma unroll
    for (int off = 16; off; off >>= 1) lsum += __shfl_down_sync(0xffffffffu, lsum, off);
    if ((tid & 31) == 0) swred[tid >> 5] = lsum;
    __syncthreads();
    if (tid == 0) atomicAdd(sumout, swred[0] + swred[1] + swred[2] + swred[3]);
}

// ---------------------------------------------------------------------------
// convt256: ConvTranspose2d k=4 s=2 p=1, NCHW, torch weight [Ci, Co, 4, 4].
// 256 thr = (16 tx, 16 ty), out tile 32 wide x 16 tall, 2 px/thread along w.
// ---------------------------------------------------------------------------
template <int COT>
__device__ __forceinline__ void ct_tap2(ull (&acc)[2][COT / 2], const float* wrow,
                                        float xa, float xb) {
    ull pa = pack2(xa), pb = pack2(xb);
    const ulonglong2* wp = (const ulonglong2*)wrow;
#pragma unroll
    for (int j = 0; j < COT / 4; ++j) {
        ulonglong2 wv = wp[j];
        acc[0][2 * j + 0] = fma2(pa, wv.x, acc[0][2 * j + 0]);
        acc[0][2 * j + 1] = fma2(pa, wv.y, acc[0][2 * j + 1]);
        acc[1][2 * j + 0] = fma2(pb, wv.x, acc[1][2 * j + 0]);
        acc[1][2 * j + 1] = fma2(pb, wv.y, acc[1][2 * j + 1]);
    }
}

template <int COT, int RELU>
__global__ void __launch_bounds__(256) convt256_k(
    const float* __restrict__ in1, const float* __restrict__ in2,
    const float* __restrict__ w, const float* __restrict__ bias,
    float* __restrict__ y, int N, int Ci1, int Ci2, int Hi, int Wi, int Co)
{
    const int Ho = Hi * 2, Wo = Wi * 2;
    __shared__ float sx[8][10][19];
    __shared__ __align__(16) float sw[8 * 16 * COT];

    const int tid = threadIdx.x;
    const int tx = tid & 15, ty = tid >> 4;
    const int cogs = (Co + COT - 1) / COT;
    const int n = blockIdx.z / cogs, cog = blockIdx.z % cogs;
    const int ho = blockIdx.y * 16 + ty;
    const int wo1 = blockIdx.x * 32 + tx;
    const int hi_base = blockIdx.y * 8 - 1;
    const int wi_base = blockIdx.x * 16 - 1;
    const int Ci = Ci1 + Ci2;

    const int ph = (ty + 1) & 1, pw = (tx + 1) & 1;
    const int ha = ((ty + 1 - ph) >> 1) + 1, hb = ha - 1;
    const int wa = ((tx + 1 - pw) >> 1) + 1, wb = wa - 1;
    const int k1 = ph * 4 + pw, k2 = k1 + 2, k3 = k1 + 8, k4 = k1 + 10;

    ull acc[2][COT / 2];
#pragma unroll
    for (int p = 0; p < 2; ++p)
#pragma unroll
        for (int j = 0; j < COT / 2; ++j) acc[p][j] = 0ULL;

    for (int ci0 = 0; ci0 < Ci; ci0 += 8) {
        __syncthreads();
        for (int idx = tid; idx < 8 * 10 * 18; idx += 256) {
            int c = idx / 180, rem = idx % 180;
            int r = rem / 18, cc = rem % 18;
            int ci = ci0 + c, hi = hi_base + r, wi = wi_base + cc;
            float v = 0.f;
            if (hi >= 0 && hi < Hi && wi >= 0 && wi < Wi) {
                if (ci < Ci1)
                    v = in1[((size_t)(n * Ci1 + ci) * Hi + hi) * Wi + wi];
                else
                    v = in2[((size_t)(n * Ci2 + (ci - Ci1)) * Hi + hi) * Wi + wi];
            }
            sx[c][r][cc] = v;
        }
        for (int idx = tid; idx < 8 * 16 * COT; idx += 256) {
            int c = idx / (16 * COT), rem = idx % (16 * COT);
            int k = rem / COT, co = rem % COT;
            int ci = ci0 + c, cg = cog * COT + co;
            sw[idx] = (cg < Co) ? w[((size_t)ci * Co + cg) * 16 + k] : 0.f;
        }
        __syncthreads();
        for (int c = 0; c < 8; ++c) {
            float x1aa = sx[c][ha][wa],     x1ab = sx[c][ha][wb];
            float x1ba = sx[c][hb][wa],     x1bb = sx[c][hb][wb];
            float x2aa = sx[c][ha][wa + 8], x2ab = sx[c][ha][wb + 8];
            float x2ba = sx[c][hb][wa + 8], x2bb = sx[c][hb][wb + 8];
            const float* wb0 = &sw[c * 16 * COT];
            ct_tap2<COT>(acc, wb0 + k1 * COT, x1aa, x2aa);
            ct_tap2<COT>(acc, wb0 + k2 * COT, x1ab, x2ab);
            ct_tap2<COT>(acc, wb0 + k3 * COT, x1ba, x2ba);
            ct_tap2<COT>(acc, wb0 + k4 * COT, x1bb, x2bb);
        }
    }
#pragma unroll
    for (int p = 0; p < 2; ++p) {
        int wo = wo1 + p * 16;
#pragma unroll
        for (int j = 0; j < COT / 2; ++j) {
            float v0, v1;
            unpack2(acc[p][j], v0, v1);
            int cg0 = cog * COT + 2 * j;
            if (cg0 < Co) {
                float r0 = v0 + bias[cg0];
                if (RELU) r0 = fmaxf(r0, 0.f);
                y[((size_t)(n * Co + cg0) * Ho + ho) * Wo + wo] = r0;
            }
            if (cg0 + 1 < Co) {
                float r1 = v1 + bias[cg0 + 1];
                if (RELU) r1 = fmaxf(r1, 0.f);
                y[((size_t)(n * Co + cg0 + 1) * Ho + ho) * Wo + wo] = r1;
            }
        }
    }
}

// ---------------------------------------------------------------------------
__global__ void loss_k(float* __restrict__ out) {
    out[0] = g_sum_t[0] * (1.f / (16384.f * 64.f)) + g_sum_b[0] * (1.f / (65536.f * 64.f));
}

// ---------------------------------------------------------------------------
static float* symf(const void* s) {
    void* p = nullptr;
    cudaGetSymbolAddress(&p, s);
    return (float*)p;
}

extern "C" void kernel_launch(void* const* d_in, const int* in_sizes, int n_in,
                              void* d_out, int out_size) {
    (void)in_sizes; (void)n_in; (void)out_size;
    const float* x       = (const float*)d_in[0];
    const float* wb1     = (const float*)d_in[1];
    const float* bb1     = (const float*)d_in[2];
    const float* wb2     = (const float*)d_in[3];
    const float* bb2     = (const float*)d_in[4];
    const float* wt1     = (const float*)d_in[5];
    const float* bt1     = (const float*)d_in[6];
    const float* wqt     = (const float*)d_in[7];
    const float* bqt     = (const float*)d_in[8];
    const float* embed_t = (const float*)d_in[9];
    const float* wdt     = (const float*)d_in[10];
    const float* bdt     = (const float*)d_in[11];
    const float* wqb     = (const float*)d_in[12];
    const float* bqb     = (const float*)d_in[13];
    const float* embed_b = (const float*)d_in[14];
    const float* wup     = (const float*)d_in[15];
    const float* bup     = (const float*)d_in[16];
    const float* wd1     = (const float*)d_in[17];
    const float* bd1     = (const float*)d_in[18];
    const float* wd2     = (const float*)d_in[19];
    const float* bd2     = (const float*)d_in[20];

    float* out = (float*)d_out;
    float* o_xhat = out;
    float* o_qt   = out + 3145728;
    float* o_qb   = out + 3145728 + 1048576;
    float* o_loss = out + 8388608;
    float* o_idt  = out + 8388609;
    float* o_idb  = out + 8388609 + 16384;

    float* enc_b1 = symf(g_enc_b1);
    float* enc_b  = symf(g_enc_b);
    float* enc_t  = symf(g_enc_t);
    float* qt     = symf(g_qt);
    float* dec_t  = symf(g_dec_t);
    float* qb     = symf(g_qb);
    float* up_t   = symf(g_up_t);
    float* h      = symf(g_h);
    float* e2t    = symf(g_e2t);
    float* e2b    = symf(g_e2b);
    float* sum_t  = symf(g_sum_t);
    float* sum_b  = symf(g_sum_b);

    prep_kernel<<<2, 512>>>(embed_t, embed_b);

    // encoder — 256-thr blocks for conv1/conv2; proven 128-thr for conv3
    conv_down256_k<32, 1><<<dim3(8, 4, 64), 256>>>(x,      wb1, bb1, enc_b1, 16,   3, 256, 256, 128);
    conv_down256_k<16, 1><<<dim3(4, 2, 128), 256>>>(enc_b1, wb2, bb2, enc_b, 16, 128, 128, 128, 128);
    conv_down2_k<16, 1><<<dim3(2, 2, 128), 128>>>(enc_b,   wt1, bt1, enc_t,  16, 128,  64,  64, 128);

    // top quantize
    conv1x1_nhwc_k<<<128, 128>>>(enc_t, nullptr, wqt, bqt, qt, 128, 0, 1024);
    quantize_k<<<1024, 128>>>(qt, embed_t, e2t, o_qt, o_idt, sum_t, 1024);

    // decoder_top + bottom quantize
    convt256_k<16, 0><<<dim3(2, 4, 64), 256>>>(o_qt, nullptr, wdt, bdt, dec_t, 16, 64, 0, 32, 32, 64);
    conv1x1_nhwc_k<<<512, 128>>>(dec_t, enc_b, wqb, bqb, qb, 64, 128, 4096);
    quantize_k<<<4096, 128>>>(qb, embed_b, e2b, o_qb, o_idb, sum_b, 4096);

    // decode
    convt256_k<16, 0><<<dim3(2, 4, 64), 256>>>(o_qt, nullptr, wup, bup, up_t, 16, 64, 0, 32, 32, 64);
    convt256_k<32, 1><<<dim3(4, 8, 32), 256>>>(up_t, o_qb,   wd1, bd1, h,    16, 64, 64, 64, 64, 64);
    convt256_k<4,  0><<<dim3(8, 16, 16), 256>>>(h,  nullptr, wd2, bd2, o_xhat, 16, 64, 0, 128, 128, 3);

    loss_k<<<1, 1>>>(o_loss);
}

// round 11
// speedup vs baseline: 1.1348x; 1.1348x over previous
#include <cuda_runtime.h>
#include <cstddef>

typedef unsigned long long ull;

// ---------------------------------------------------------------------------
// Packed f32x2 helpers (FFMA2 — only reachable via PTX)
// ---------------------------------------------------------------------------
__device__ __forceinline__ ull fma2(ull a, ull b, ull c) {
    ull d;
    asm("fma.rn.f32x2 %0, %1, %2, %3;" : "=l"(d) : "l"(a), "l"(b), "l"(c));
    return d;
}
__device__ __forceinline__ ull pack2(float x) {
    ull d;
    asm("mov.b64 %0, {%1, %1};" : "=l"(d) : "f"(x));
    return d;
}
__device__ __forceinline__ void unpack2(ull v, float& lo, float& hi) {
    asm("mov.b64 {%0, %1}, %2;" : "=f"(lo), "=f"(hi) : "l"(v));
}

// ---------------------------------------------------------------------------
// Scratch (device globals — no runtime allocation allowed)
// ---------------------------------------------------------------------------
__device__ float g_enc_b1[16 * 128 * 128 * 128];
__device__ float g_enc_b [16 * 128 * 64 * 64];
__device__ float g_enc_t [16 * 128 * 32 * 32];
__device__ float g_qt    [16 * 32 * 32 * 64];
__device__ float g_dec_t [16 * 64 * 64 * 64];
__device__ float g_qb    [16 * 64 * 64 * 64];
__device__ float g_up_t  [16 * 64 * 64 * 64];
__device__ float g_h     [16 * 64 * 128 * 128];
__device__ float g_e2t[512];
__device__ float g_e2b[512];
__device__ float g_sum_t[1];
__device__ float g_sum_b[1];

// ---------------------------------------------------------------------------
__global__ void prep_kernel(const float* __restrict__ et, const float* __restrict__ eb) {
    int t = blockIdx.x * blockDim.x + threadIdx.x;
    if (t < 512) {
        float s = 0.f;
        for (int d = 0; d < 64; ++d) { float v = et[d * 512 + t]; s = fmaf(v, v, s); }
        g_e2t[t] = s;
    } else if (t < 1024) {
        int k = t - 512;
        float s = 0.f;
        for (int d = 0; d < 64; ++d) { float v = eb[d * 512 + k]; s = fmaf(v, v, s); }
        g_e2b[k] = s;
    }
    if (t == 0) { g_sum_t[0] = 0.f; g_sum_b[0] = 0.f; }
}

// ---------------------------------------------------------------------------
// 4x4 stride-2 pad-1 downsample conv, NCHW (R3 body). Block 128 thr =
// 16x16 out tile (2 rows/thread), COG output channels/block, f32x2 FMA.
// ---------------------------------------------------------------------------
template <int COG, int RELU>
__global__ void __launch_bounds__(128) conv_down2_k(
    const float* __restrict__ x, const float* __restrict__ w,
    const float* __restrict__ bias, float* __restrict__ y,
    int N, int Ci, int Hi, int Wi, int Co)
{
    const int Ho = Hi >> 1, Wo = Wi >> 1;
    __shared__ float sx[4][34][35];
    __shared__ __align__(16) float sw[16 * 4 * COG];

    const int tid = threadIdx.x;
    const int tx = tid & 15, ty = tid >> 4;
    const int cogs = Co / COG;
    const int n = blockIdx.z / cogs, cog = blockIdx.z % cogs;
    const int wo = blockIdx.x * 16 + tx;
    const int ho0 = blockIdx.y * 16 + ty;
    const int hi0 = blockIdx.y * 32 - 1, wi0 = blockIdx.x * 32 - 1;

    ull acc[2][COG / 2];
#pragma unroll
    for (int p = 0; p < 2; ++p)
#pragma unroll
        for (int j = 0; j < COG / 2; ++j) acc[p][j] = 0ULL;

    for (int ci0 = 0; ci0 < Ci; ci0 += 4) {
        __syncthreads();
        for (int idx = tid; idx < 4 * 34 * 34; idx += 128) {
            int c = idx / 1156, rem = idx % 1156;
            int r = rem / 34, cc = rem % 34;
            int ci = ci0 + c, hi = hi0 + r, wi = wi0 + cc;
            float v = 0.f;
            if (ci < Ci && hi >= 0 && hi < Hi && wi >= 0 && wi < Wi)
                v = x[((size_t)(n * Ci + ci) * Hi + hi) * Wi + wi];
            sx[c][r][cc] = v;
        }
        for (int idx = tid; idx < 16 * 4 * COG; idx += 128) {
            int k = idx / (4 * COG), rem = idx % (4 * COG);
            int c = rem / COG, co = rem % COG;
            int ci = ci0 + c;
            sw[idx] = (ci < Ci) ? w[((size_t)(cog * COG + co) * Ci + ci) * 16 + k] : 0.f;
        }
        __syncthreads();
#pragma unroll
        for (int c = 0; c < 4; ++c) {
#pragma unroll
            for (int k = 0; k < 16; ++k) {
                const int kh = k >> 2, kw = k & 3;
                float f0 = sx[c][2 * ty + kh][2 * tx + kw];
                float f1 = sx[c][2 * ty + 16 + kh][2 * tx + kw];
                ull xp0 = pack2(f0), xp1 = pack2(f1);
                const ulonglong2* wp = (const ulonglong2*)&sw[(k * 4 + c) * COG];
#pragma unroll
                for (int j = 0; j < COG / 4; ++j) {
                    ulonglong2 wv = wp[j];
                    acc[0][2 * j + 0] = fma2(xp0, wv.x, acc[0][2 * j + 0]);
                    acc[0][2 * j + 1] = fma2(xp0, wv.y, acc[0][2 * j + 1]);
                    acc[1][2 * j + 0] = fma2(xp1, wv.x, acc[1][2 * j + 0]);
                    acc[1][2 * j + 1] = fma2(xp1, wv.y, acc[1][2 * j + 1]);
                }
            }
        }
    }
#pragma unroll
    for (int p = 0; p < 2; ++p) {
        int ho = ho0 + p * 8;
#pragma unroll
        for (int j = 0; j < COG / 2; ++j) {
            float v0, v1;
            unpack2(acc[p][j], v0, v1);
            int cg0 = cog * COG + 2 * j;
            v0 += bias[cg0];
            v1 += bias[cg0 + 1];
            if (RELU) { v0 = fmaxf(v0, 0.f); v1 = fmaxf(v1, 0.f); }
            y[((size_t)(n * Co + cg0) * Ho + ho) * Wo + wo] = v0;
            y[((size_t)(n * Co + cg0 + 1) * Ho + ho) * Wo + wo] = v1;
        }
    }
}

// ---------------------------------------------------------------------------
// 1x1 conv over (optionally) two concatenated inputs, output NHWC, Co = 64.
// 1 pixel/thread.
// ---------------------------------------------------------------------------
__global__ void __launch_bounds__(128) conv1x1_nhwc_k(
    const float* __restrict__ in1, const float* __restrict__ in2,
    const float* __restrict__ w, const float* __restrict__ bias,
    float* __restrict__ y, int Ci1, int Ci2, int HW)
{
    __shared__ __align__(16) float sw[192 * 64]; // [ci][co]
    const int Ci = Ci1 + Ci2;
    const int tid = threadIdx.x;
    for (int idx = tid; idx < Ci * 64; idx += 128) {
        int ci = idx >> 6, co = idx & 63;
        sw[idx] = w[(size_t)co * Ci + ci];
    }
    __syncthreads();

    const int p = blockIdx.x * 128 + tid;
    const int n = p / HW, hw = p % HW;

    ull acc[32];
#pragma unroll
    for (int j = 0; j < 32; ++j) acc[j] = 0ULL;

    {
        const float* a0 = in1 + (size_t)n * Ci1 * HW + hw;
        for (int ci = 0; ci < Ci1; ++ci) {
            ull xp0 = pack2(a0[(size_t)ci * HW]);
            const ulonglong2* wp = (const ulonglong2*)&sw[ci * 64];
#pragma unroll
            for (int j = 0; j < 16; ++j) {
                ulonglong2 wv = wp[j];
                acc[2 * j + 0] = fma2(xp0, wv.x, acc[2 * j + 0]);
                acc[2 * j + 1] = fma2(xp0, wv.y, acc[2 * j + 1]);
            }
        }
    }
    if (Ci2 > 0) {
        const float* a0 = in2 + (size_t)n * Ci2 * HW + hw;
        for (int ci = 0; ci < Ci2; ++ci) {
            ull xp0 = pack2(a0[(size_t)ci * HW]);
            const ulonglong2* wp = (const ulonglong2*)&sw[(Ci1 + ci) * 64];
#pragma unroll
            for (int j = 0; j < 16; ++j) {
                ulonglong2 wv = wp[j];
                acc[2 * j + 0] = fma2(xp0, wv.x, acc[2 * j + 0]);
                acc[2 * j + 1] = fma2(xp0, wv.y, acc[2 * j + 1]);
            }
        }
    }
    float4* out4 = (float4*)&y[(size_t)p * 64];
#pragma unroll
    for (int j4 = 0; j4 < 16; ++j4) {
        float a, b, c, d;
        unpack2(acc[2 * j4 + 0], a, b);
        unpack2(acc[2 * j4 + 1], c, d);
        out4[j4] = make_float4(a + bias[4 * j4 + 0], b + bias[4 * j4 + 1],
                               c + bias[4 * j4 + 2], d + bias[4 * j4 + 3]);
    }
}

// ---------------------------------------------------------------------------
// Vector quantize (R3 body)
// ---------------------------------------------------------------------------
__global__ void __launch_bounds__(128) quantize_k(
    const float* __restrict__ z, const float* __restrict__ embed,
    const float* __restrict__ e2, float* __restrict__ qout,
    float* __restrict__ idout, float* __restrict__ sumout, int HW)
{
    __shared__ __align__(16) float sz[16 * 68];
    __shared__ __align__(16) float se[64 * 128];
    __shared__ float se2[128];
    __shared__ float swred[4];

    const int tid = threadIdx.x;
    const int m0 = blockIdx.x * 16;

    for (int idx = tid; idx < 16 * 64; idx += 128) {
        int v = idx >> 6, d = idx & 63;
        sz[v * 68 + d] = z[(size_t)(m0 + v) * 64 + d];
    }
    __syncthreads();

    const int v = tid >> 3, g = tid & 7;

    float z2 = 0.f;
    for (int d = 0; d < 64; ++d) { float t = sz[v * 68 + d]; z2 = fmaf(t, t, z2); }

    float bestd = 3.4e38f;
    int bestk = 0;

    for (int kc = 0; kc < 512; kc += 128) {
        __syncthreads();
        for (int idx = tid; idx < 64 * 128; idx += 128)
            se[idx] = embed[(size_t)(idx >> 7) * 512 + kc + (idx & 127)];
        if (tid < 128) se2[tid] = e2[kc + tid];
        __syncthreads();

        ull dotp[8];
#pragma unroll
        for (int j = 0; j < 8; ++j) dotp[j] = 0ULL;
        for (int d = 0; d < 64; ++d) {
            ull zp = pack2(sz[v * 68 + d]);
            const ulonglong2* ep = (const ulonglong2*)&se[d * 128 + g * 16];
#pragma unroll
            for (int m = 0; m < 4; ++m) {
                ulonglong2 ev = ep[m];
                dotp[2 * m + 0] = fma2(zp, ev.x, dotp[2 * m + 0]);
                dotp[2 * m + 1] = fma2(zp, ev.y, dotp[2 * m + 1]);
            }
        }
#pragma unroll
        for (int m = 0; m < 8; ++m) {
            float d0, d1;
            unpack2(dotp[m], d0, d1);
            int j0 = 2 * m;
            float dist0 = (z2 - 2.f * d0) + se2[g * 16 + j0];
            float dist1 = (z2 - 2.f * d1) + se2[g * 16 + j0 + 1];
            int k0 = kc + g * 16 + j0;
            if (dist0 < bestd) { bestd = dist0; bestk = k0; }
            if (dist1 < bestd) { bestd = dist1; bestk = k0 + 1; }
        }
    }

#pragma unroll
    for (int off = 4; off; off >>= 1) {
        float od = __shfl_down_sync(0xffffffffu, bestd, off, 8);
        int   ok = __shfl_down_sync(0xffffffffu, bestk, off, 8);
        if (od < bestd || (od == bestd && ok < bestk)) { bestd = od; bestk = ok; }
    }
    bestk = __shfl_sync(0xffffffffu, bestk, 0, 8);

    const int m = m0 + v;
    const int n = m / HW, hw = m % HW;
    float lsum = 0.f;
    float* qbase = qout + (size_t)n * 64 * HW + hw;
#pragma unroll
    for (int dd = 0; dd < 8; ++dd) {
        int d = g * 8 + dd;
        float q = embed[(size_t)d * 512 + bestk];
        float zv = sz[v * 68 + d];
        float df = q - zv;
        lsum = fmaf(df, df, lsum);
        qbase[(size_t)d * HW] = zv + (q - zv);
    }
    if (g == 0) idout[m] = (float)bestk;

#pragma unroll
    for (int off = 16; off; off >>= 1) lsum += __shfl_down_sync(0xffffffffu, lsum, off);
    if ((tid & 31) == 0) swred[tid >> 5] = lsum;
    __syncthreads();
    if (tid == 0) atomicAdd(sumout, swred[0] + swred[1] + swred[2] + swred[3]);
}

// ---------------------------------------------------------------------------
// ConvTranspose2d k=4 s=2 p=1, NCHW, torch weight [Ci, Co, 4, 4] (R3 body).
// ---------------------------------------------------------------------------
template <int COT>
__device__ __forceinline__ void ct_tap2(ull (&acc)[2][COT / 2], const float* wrow,
                                        float xa, float xb) {
    ull pa = pack2(xa), pb = pack2(xb);
    const ulonglong2* wp = (const ulonglong2*)wrow;
#pragma unroll
    for (int j = 0; j < COT / 4; ++j) {
        ulonglong2 wv = wp[j];
        acc[0][2 * j + 0] = fma2(pa, wv.x, acc[0][2 * j + 0]);
        acc[0][2 * j + 1] = fma2(pa, wv.y, acc[0][2 * j + 1]);
        acc[1][2 * j + 0] = fma2(pb, wv.x, acc[1][2 * j + 0]);
        acc[1][2 * j + 1] = fma2(pb, wv.y, acc[1][2 * j + 1]);
    }
}

template <int COT, int RELU>
__global__ void __launch_bounds__(128) convt2_k(
    const float* __restrict__ in1, const float* __restrict__ in2,
    const float* __restrict__ w, const float* __restrict__ bias,
    float* __restrict__ y, int N, int Ci1, int Ci2, int Hi, int Wi, int Co)
{
    const int Ho = Hi * 2, Wo = Wi * 2;
    __shared__ float sx[8][6][19];
    __shared__ __align__(16) float sw[8 * 16 * COT];

    const int tid = threadIdx.x;
    const int tx = tid & 15, ty = tid >> 4;
    const int cogs = (Co + COT - 1) / COT;
    const int n = blockIdx.z / cogs, cog = blockIdx.z % cogs;
    const int ho = blockIdx.y * 8 + ty;
    const int wo1 = blockIdx.x * 32 + tx;
    const int hi_base = blockIdx.y * 4 - 1;
    const int wi_base = blockIdx.x * 16 - 1;
    const int Ci = Ci1 + Ci2;

    const int ph = (ty + 1) & 1, pw = (tx + 1) & 1;
    const int ha = ((ty + 1 - ph) >> 1) + 1, hb = ha - 1;
    const int wa = ((tx + 1 - pw) >> 1) + 1, wb = wa - 1;
    const int k1 = ph * 4 + pw, k2 = k1 + 2, k3 = k1 + 8, k4 = k1 + 10;

    ull acc[2][COT / 2];
#pragma unroll
    for (int p = 0; p < 2; ++p)
#pragma unroll
        for (int j = 0; j < COT / 2; ++j) acc[p][j] = 0ULL;

    for (int ci0 = 0; ci0 < Ci; ci0 += 8) {
        __syncthreads();
        for (int idx = tid; idx < 8 * 6 * 18; idx += 128) {
            int c = idx / 108, rem = idx % 108;
            int r = rem / 18, cc = rem % 18;
            int ci = ci0 + c, hi = hi_base + r, wi = wi_base + cc;
            float v = 0.f;
            if (hi >= 0 && hi < Hi && wi >= 0 && wi < Wi) {
                if (ci < Ci1)
                    v = in1[((size_t)(n * Ci1 + ci) * Hi + hi) * Wi + wi];
                else
                    v = in2[((size_t)(n * Ci2 + (ci - Ci1)) * Hi + hi) * Wi + wi];
            }
            sx[c][r][cc] = v;
        }
        for (int idx = tid; idx < 8 * 16 * COT; idx += 128) {
            int c = idx / (16 * COT), rem = idx % (16 * COT);
            int k = rem / COT, co = rem % COT;
            int ci = ci0 + c, cg = cog * COT + co;
            sw[idx] = (cg < Co) ? w[((size_t)ci * Co + cg) * 16 + k] : 0.f;
        }
        __syncthreads();
        for (int c = 0; c < 8; ++c) {
            float x1aa = sx[c][ha][wa],     x1ab = sx[c][ha][wb];
            float x1ba = sx[c][hb][wa],     x1bb = sx[c][hb][wb];
            float x2aa = sx[c][ha][wa + 8], x2ab = sx[c][ha][wb + 8];
            float x2ba = sx[c][hb][wa + 8], x2bb = sx[c][hb][wb + 8];
            const float* wb0 = &sw[c * 16 * COT];
            ct_tap2<COT>(acc, wb0 + k1 * COT, x1aa, x2aa);
            ct_tap2<COT>(acc, wb0 + k2 * COT, x1ab, x2ab);
            ct_tap2<COT>(acc, wb0 + k3 * COT, x1ba, x2ba);
            ct_tap2<COT>(acc, wb0 + k4 * COT, x1bb, x2bb);
        }
    }
#pragma unroll
    for (int p = 0; p < 2; ++p) {
        int wo = wo1 + p * 16;
#pragma unroll
        for (int j = 0; j < COT / 2; ++j) {
            float v0, v1;
            unpack2(acc[p][j], v0, v1);
            int cg0 = cog * COT + 2 * j;
            if (cg0 < Co) {
                float r0 = v0 + bias[cg0];
                if (RELU) r0 = fmaxf(r0, 0.f);
                y[((size_t)(n * Co + cg0) * Ho + ho) * Wo + wo] = r0;
            }
            if (cg0 + 1 < Co) {
                float r1 = v1 + bias[cg0 + 1];
                if (RELU) r1 = fmaxf(r1, 0.f);
                y[((size_t)(n * Co + cg0 + 1) * Ho + ho) * Wo + wo] = r1;
            }
        }
    }
}

// ---------------------------------------------------------------------------
__global__ void loss_k(float* __restrict__ out) {
    out[0] = g_sum_t[0] * (1.f / (16384.f * 64.f)) + g_sum_b[0] * (1.f / (65536.f * 64.f));
}

// ---------------------------------------------------------------------------
static float* symf(const void* s) {
    void* p = nullptr;
    cudaGetSymbolAddress(&p, s);
    return (float*)p;
}

extern "C" void kernel_launch(void* const* d_in, const int* in_sizes, int n_in,
                              void* d_out, int out_size) {
    (void)in_sizes; (void)n_in; (void)out_size;
    const float* x       = (const float*)d_in[0];
    const float* wb1     = (const float*)d_in[1];
    const float* bb1     = (const float*)d_in[2];
    const float* wb2     = (const float*)d_in[3];
    const float* bb2     = (const float*)d_in[4];
    const float* wt1     = (const float*)d_in[5];
    const float* bt1     = (const float*)d_in[6];
    const float* wqt     = (const float*)d_in[7];
    const float* bqt     = (const float*)d_in[8];
    const float* embed_t = (const float*)d_in[9];
    const float* wdt     = (const float*)d_in[10];
    const float* bdt     = (const float*)d_in[11];
    const float* wqb     = (const float*)d_in[12];
    const float* bqb     = (const float*)d_in[13];
    const float* embed_b = (const float*)d_in[14];
    const float* wup     = (const float*)d_in[15];
    const float* bup     = (const float*)d_in[16];
    const float* wd1     = (const float*)d_in[17];
    const float* bd1     = (const float*)d_in[18];
    const float* wd2     = (const float*)d_in[19];
    const float* bd2     = (const float*)d_in[20];

    float* out = (float*)d_out;
    float* o_xhat = out;
    float* o_qt   = out + 3145728;
    float* o_qb   = out + 3145728 + 1048576;
    float* o_loss = out + 8388608;
    float* o_idt  = out + 8388609;
    float* o_idb  = out + 8388609 + 16384;

    float* enc_b1 = symf(g_enc_b1);
    float* enc_b  = symf(g_enc_b);
    float* enc_t  = symf(g_enc_t);
    float* qt     = symf(g_qt);
    float* dec_t  = symf(g_dec_t);
    float* qb     = symf(g_qb);
    float* up_t   = symf(g_up_t);
    float* h      = symf(g_h);
    float* e2t    = symf(g_e2t);
    float* e2b    = symf(g_e2b);
    float* sum_t  = symf(g_sum_t);
    float* sum_b  = symf(g_sum_b);

    prep_kernel<<<2, 512>>>(embed_t, embed_b);

    // encoder — R9 config except conv3 reverted to proven COG=16
    conv_down2_k<32, 1><<<dim3(8, 8, 64), 128>>>(x,      wb1, bb1, enc_b1, 16,   3, 256, 256, 128);
    conv_down2_k<16, 1><<<dim3(4, 4, 128), 128>>>(enc_b1, wb2, bb2, enc_b,  16, 128, 128, 128, 128);
    conv_down2_k<16, 1><<<dim3(2, 2, 128), 128>>>(enc_b,  wt1, bt1, enc_t,  16, 128,  64,  64, 128);

    // top quantize
    conv1x1_nhwc_k<<<128, 128>>>(enc_t, nullptr, wqt, bqt, qt, 128, 0, 1024);
    quantize_k<<<1024, 128>>>(qt, embed_t, e2t, o_qt, o_idt, sum_t, 1024);

    // decoder_top + bottom quantize
    convt2_k<16, 0><<<dim3(2, 8, 64), 128>>>(o_qt, nullptr, wdt, bdt, dec_t, 16, 64, 0, 32, 32, 64);
    conv1x1_nhwc_k<<<512, 128>>>(dec_t, enc_b, wqb, bqb, qb, 64, 128, 4096);
    quantize_k<<<4096, 128>>>(qb, embed_b, e2b, o_qb, o_idb, sum_b, 4096);

    // decode — wd1 split COT 32->16 (grid 2048->4096, lower reg pressure)
    convt2_k<16, 0><<<dim3(2, 8, 64), 128>>>(o_qt, nullptr, wup, bup, up_t, 16, 64, 0, 32, 32, 64);
    convt2_k<16, 1><<<dim3(4, 16, 64), 128>>>(up_t, o_qb,   wd1, bd1, h,    16, 64, 64, 64, 64, 64);
    convt2_k<4,  0><<<dim3(8, 32, 16), 128>>>(h,   nullptr, wd2, bd2, o_xhat, 16, 64, 0, 128, 128, 3);

    loss_k<<<1, 1>>>(o_loss);
}

// round 12
// speedup vs baseline: 1.3344x; 1.1759x over previous
#include <cuda_runtime.h>
#include <cstddef>

typedef unsigned long long ull;

// ---------------------------------------------------------------------------
// Packed f32x2 helpers (FFMA2 — only reachable via PTX)
// ---------------------------------------------------------------------------
__device__ __forceinline__ ull fma2(ull a, ull b, ull c) {
    ull d;
    asm("fma.rn.f32x2 %0, %1, %2, %3;" : "=l"(d) : "l"(a), "l"(b), "l"(c));
    return d;
}
__device__ __forceinline__ ull pack2(float x) {
    ull d;
    asm("mov.b64 %0, {%1, %1};" : "=l"(d) : "f"(x));
    return d;
}
__device__ __forceinline__ void unpack2(ull v, float& lo, float& hi) {
    asm("mov.b64 {%0, %1}, %2;" : "=f"(lo), "=f"(hi) : "l"(v));
}

// ---------------------------------------------------------------------------
// Scratch (device globals — no runtime allocation allowed)
// ---------------------------------------------------------------------------
__device__ float g_enc_b1[16 * 128 * 128 * 128];
__device__ float g_enc_b [16 * 128 * 64 * 64];
__device__ float g_enc_t [16 * 128 * 32 * 32];
__device__ float g_qt    [16 * 32 * 32 * 64];
__device__ float g_dec_t [16 * 64 * 64 * 64];
__device__ float g_qb    [16 * 64 * 64 * 64];
__device__ float g_up_t  [16 * 64 * 64 * 64];
__device__ float g_h     [16 * 64 * 128 * 128];
__device__ float g_e2t[512];
__device__ float g_e2b[512];
__device__ float g_sum_t[1];
__device__ float g_sum_b[1];

// ---------------------------------------------------------------------------
__global__ void prep_kernel(const float* __restrict__ et, const float* __restrict__ eb) {
    int t = blockIdx.x * blockDim.x + threadIdx.x;
    if (t < 512) {
        float s = 0.f;
        for (int d = 0; d < 64; ++d) { float v = et[d * 512 + t]; s = fmaf(v, v, s); }
        g_e2t[t] = s;
    } else if (t < 1024) {
        int k = t - 512;
        float s = 0.f;
        for (int d = 0; d < 64; ++d) { float v = eb[d * 512 + k]; s = fmaf(v, v, s); }
        g_e2b[k] = s;
    }
    if (t == 0) { g_sum_t[0] = 0.f; g_sum_b[0] = 0.f; }
}

// ---------------------------------------------------------------------------
// 4x4 stride-2 pad-1 downsample conv, NCHW. Block 128 thr = 16x16 out tile
// (2 rows/thread), COG output channels/block, f32x2 FMA.
// Divmod-free flat staging: thread owns (c = tid>>5 & 3, cc = tid & 31),
// r is the unrolled loop counter; 2 leftover columns via pow2-decoded tail.
// ---------------------------------------------------------------------------
template <int COG, int RELU>
__global__ void __launch_bounds__(128) conv_down2_k(
    const float* __restrict__ x, const float* __restrict__ w,
    const float* __restrict__ bias, float* __restrict__ y,
    int N, int Ci, int Hi, int Wi, int Co)
{
    const int Ho = Hi >> 1, Wo = Wi >> 1;
    __shared__ float sx[4][34][35];
    __shared__ __align__(16) float sw[16 * 4 * COG];

    const int tid = threadIdx.x;
    const int tx = tid & 15, ty = tid >> 4;
    const int scc = tid & 31;            // staging column
    const int scs = (tid >> 5) & 3;      // staging channel
    const int cogs = Co / COG;
    const int n = blockIdx.z / cogs, cog = blockIdx.z % cogs;
    const int wo = blockIdx.x * 16 + tx;
    const int ho0 = blockIdx.y * 16 + ty;
    const int hi0 = blockIdx.y * 32 - 1, wi0 = blockIdx.x * 32 - 1;

    const int swi = wi0 + scc;
    const bool swok = (swi >= 0) && (swi < Wi);

    ull acc[2][COG / 2];
#pragma unroll
    for (int p = 0; p < 2; ++p)
#pragma unroll
        for (int j = 0; j < COG / 2; ++j) acc[p][j] = 0ULL;

    for (int ci0 = 0; ci0 < Ci; ci0 += 4) {
        __syncthreads();
        // ---- input staging: main 32 columns, divmod-free ----
        {
            const int ci = ci0 + scs;
            const bool cok = (ci < Ci);
            const float* src = x + (size_t)(n * Ci + ci) * Hi * Wi + swi;
#pragma unroll
            for (int r = 0; r < 34; ++r) {
                const int hi = hi0 + r;
                float v = 0.f;
                if (cok && swok && hi >= 0 && hi < Hi)
                    v = src[(size_t)hi * Wi];
                sx[scs][r][scc] = v;
            }
        }
        // ---- input staging: columns 32,33 (pow2 decode: 272 = 34*8) ----
        for (int idx = tid; idx < 272; idx += 128) {
            const int r = idx >> 3;
            const int c = (idx >> 1) & 3;
            const int cc = 32 + (idx & 1);
            const int ci = ci0 + c;
            const int hi = hi0 + r, wi = wi0 + cc;
            float v = 0.f;
            if (ci < Ci && hi >= 0 && hi < Hi && wi >= 0 && wi < Wi)
                v = x[((size_t)(n * Ci + ci) * Hi + hi) * Wi + wi];
            sx[c][r][cc] = v;
        }
        // ---- weight staging (pow2 divisors -> free) ----
        for (int idx = tid; idx < 16 * 4 * COG; idx += 128) {
            int k = idx / (4 * COG), rem = idx % (4 * COG);
            int c = rem / COG, co = rem % COG;
            int ci = ci0 + c;
            sw[idx] = (ci < Ci) ? w[((size_t)(cog * COG + co) * Ci + ci) * 16 + k] : 0.f;
        }
        __syncthreads();
#pragma unroll
        for (int c = 0; c < 4; ++c) {
#pragma unroll
            for (int k = 0; k < 16; ++k) {
                const int kh = k >> 2, kw = k & 3;
                float f0 = sx[c][2 * ty + kh][2 * tx + kw];
                float f1 = sx[c][2 * ty + 16 + kh][2 * tx + kw];
                ull xp0 = pack2(f0), xp1 = pack2(f1);
                const ulonglong2* wp = (const ulonglong2*)&sw[(k * 4 + c) * COG];
#pragma unroll
                for (int j = 0; j < COG / 4; ++j) {
                    ulonglong2 wv = wp[j];
                    acc[0][2 * j + 0] = fma2(xp0, wv.x, acc[0][2 * j + 0]);
                    acc[0][2 * j + 1] = fma2(xp0, wv.y, acc[0][2 * j + 1]);
                    acc[1][2 * j + 0] = fma2(xp1, wv.x, acc[1][2 * j + 0]);
                    acc[1][2 * j + 1] = fma2(xp1, wv.y, acc[1][2 * j + 1]);
                }
            }
        }
    }
#pragma unroll
    for (int p = 0; p < 2; ++p) {
        int ho = ho0 + p * 8;
#pragma unroll
        for (int j = 0; j < COG / 2; ++j) {
            float v0, v1;
            unpack2(acc[p][j], v0, v1);
            int cg0 = cog * COG + 2 * j;
            v0 += bias[cg0];
            v1 += bias[cg0 + 1];
            if (RELU) { v0 = fmaxf(v0, 0.f); v1 = fmaxf(v1, 0.f); }
            y[((size_t)(n * Co + cg0) * Ho + ho) * Wo + wo] = v0;
            y[((size_t)(n * Co + cg0 + 1) * Ho + ho) * Wo + wo] = v1;
        }
    }
}

// ---------------------------------------------------------------------------
// 1x1 conv over (optionally) two concatenated inputs, output NHWC, Co = 64.
// 1 pixel/thread.
// ---------------------------------------------------------------------------
__global__ void __launch_bounds__(128) conv1x1_nhwc_k(
    const float* __restrict__ in1, const float* __restrict__ in2,
    const float* __restrict__ w, const float* __restrict__ bias,
    float* __restrict__ y, int Ci1, int Ci2, int HW)
{
    __shared__ __align__(16) float sw[192 * 64]; // [ci][co]
    const int Ci = Ci1 + Ci2;
    const int tid = threadIdx.x;
    for (int idx = tid; idx < Ci * 64; idx += 128) {
        int ci = idx >> 6, co = idx & 63;
        sw[idx] = w[(size_t)co * Ci + ci];
    }
    __syncthreads();

    const int p = blockIdx.x * 128 + tid;
    const int n = p / HW, hw = p % HW;

    ull acc[32];
#pragma unroll
    for (int j = 0; j < 32; ++j) acc[j] = 0ULL;

    {
        const float* a0 = in1 + (size_t)n * Ci1 * HW + hw;
        for (int ci = 0; ci < Ci1; ++ci) {
            ull xp0 = pack2(a0[(size_t)ci * HW]);
            const ulonglong2* wp = (const ulonglong2*)&sw[ci * 64];
#pragma unroll
            for (int j = 0; j < 16; ++j) {
                ulonglong2 wv = wp[j];
                acc[2 * j + 0] = fma2(xp0, wv.x, acc[2 * j + 0]);
                acc[2 * j + 1] = fma2(xp0, wv.y, acc[2 * j + 1]);
            }
        }
    }
    if (Ci2 > 0) {
        const float* a0 = in2 + (size_t)n * Ci2 * HW + hw;
        for (int ci = 0; ci < Ci2; ++ci) {
            ull xp0 = pack2(a0[(size_t)ci * HW]);
            const ulonglong2* wp = (const ulonglong2*)&sw[(Ci1 + ci) * 64];
#pragma unroll
            for (int j = 0; j < 16; ++j) {
                ulonglong2 wv = wp[j];
                acc[2 * j + 0] = fma2(xp0, wv.x, acc[2 * j + 0]);
                acc[2 * j + 1] = fma2(xp0, wv.y, acc[2 * j + 1]);
            }
        }
    }
    float4* out4 = (float4*)&y[(size_t)p * 64];
#pragma unroll
    for (int j4 = 0; j4 < 16; ++j4) {
        float a, b, c, d;
        unpack2(acc[2 * j4 + 0], a, b);
        unpack2(acc[2 * j4 + 1], c, d);
        out4[j4] = make_float4(a + bias[4 * j4 + 0], b + bias[4 * j4 + 1],
                               c + bias[4 * j4 + 2], d + bias[4 * j4 + 3]);
    }
}

// ---------------------------------------------------------------------------
// Vector quantize (R3 body)
// ---------------------------------------------------------------------------
__global__ void __launch_bounds__(128) quantize_k(
    const float* __restrict__ z, const float* __restrict__ embed,
    const float* __restrict__ e2, float* __restrict__ qout,
    float* __restrict__ idout, float* __restrict__ sumout, int HW)
{
    __shared__ __align__(16) float sz[16 * 68];
    __shared__ __align__(16) float se[64 * 128];
    __shared__ float se2[128];
    __shared__ float swred[4];

    const int tid = threadIdx.x;
    const int m0 = blockIdx.x * 16;

    for (int idx = tid; idx < 16 * 64; idx += 128) {
        int v = idx >> 6, d = idx & 63;
        sz[v * 68 + d] = z[(size_t)(m0 + v) * 64 + d];
    }
    __syncthreads();

    const int v = tid >> 3, g = tid & 7;

    float z2 = 0.f;
    for (int d = 0; d < 64; ++d) { float t = sz[v * 68 + d]; z2 = fmaf(t, t, z2); }

    float bestd = 3.4e38f;
    int bestk = 0;

    for (int kc = 0; kc < 512; kc += 128) {
        __syncthreads();
        for (int idx = tid; idx < 64 * 128; idx += 128)
            se[idx] = embed[(size_t)(idx >> 7) * 512 + kc + (idx & 127)];
        if (tid < 128) se2[tid] = e2[kc + tid];
        __syncthreads();

        ull dotp[8];
#pragma unroll
        for (int j = 0; j < 8; ++j) dotp[j] = 0ULL;
        for (int d = 0; d < 64; ++d) {
            ull zp = pack2(sz[v * 68 + d]);
            const ulonglong2* ep = (const ulonglong2*)&se[d * 128 + g * 16];
#pragma unroll
            for (int m = 0; m < 4; ++m) {
                ulonglong2 ev = ep[m];
                dotp[2 * m + 0] = fma2(zp, ev.x, dotp[2 * m + 0]);
                dotp[2 * m + 1] = fma2(zp, ev.y, dotp[2 * m + 1]);
            }
        }
#pragma unroll
        for (int m = 0; m < 8; ++m) {
            float d0, d1;
            unpack2(dotp[m], d0, d1);
            int j0 = 2 * m;
            float dist0 = (z2 - 2.f * d0) + se2[g * 16 + j0];
            float dist1 = (z2 - 2.f * d1) + se2[g * 16 + j0 + 1];
            int k0 = kc + g * 16 + j0;
            if (dist0 < bestd) { bestd = dist0; bestk = k0; }
            if (dist1 < bestd) { bestd = dist1; bestk = k0 + 1; }
        }
    }

#pragma unroll
    for (int off = 4; off; off >>= 1) {
        float od = __shfl_down_sync(0xffffffffu, bestd, off, 8);
        int   ok = __shfl_down_sync(0xffffffffu, bestk, off, 8);
        if (od < bestd || (od == bestd && ok < bestk)) { bestd = od; bestk = ok; }
    }
    bestk = __shfl_sync(0xffffffffu, bestk, 0, 8);

    const int m = m0 + v;
    const int n = m / HW, hw = m % HW;
    float lsum = 0.f;
    float* qbase = qout + (size_t)n * 64 * HW + hw;
#pragma unroll
    for (int dd = 0; dd < 8; ++dd) {
        int d = g * 8 + dd;
        float q = embed[(size_t)d * 512 + bestk];
        float zv = sz[v * 68 + d];
        float df = q - zv;
        lsum = fmaf(df, df, lsum);
        qbase[(size_t)d * HW] = zv + (q - zv);
    }
    if (g == 0) idout[m] = (float)bestk;

#pragma unroll
    for (int off = 16; off; off >>= 1) lsum += __shfl_down_sync(0xffffffffu, lsum, off);
    if ((tid & 31) == 0) swred[tid >> 5] = lsum;
    __syncthreads();
    if (tid == 0) atomicAdd(sumout, swred[0] + swred[1] + swred[2] + swred[3]);
}

// ---------------------------------------------------------------------------
// ConvTranspose2d k=4 s=2 p=1, NCHW, torch weight [Ci, Co, 4, 4].
// Divmod-free flat staging (16-col main + 2-col tail, pow2 decode).
// ---------------------------------------------------------------------------
template <int COT>
__device__ __forceinline__ void ct_tap2(ull (&acc)[2][COT / 2], const float* wrow,
                                        float xa, float xb) {
    ull pa = pack2(xa), pb = pack2(xb);
    const ulonglong2* wp = (const ulonglong2*)wrow;
#pragma unroll
    for (int j = 0; j < COT / 4; ++j) {
        ulonglong2 wv = wp[j];
        acc[0][2 * j + 0] = fma2(pa, wv.x, acc[0][2 * j + 0]);
        acc[0][2 * j + 1] = fma2(pa, wv.y, acc[0][2 * j + 1]);
        acc[1][2 * j + 0] = fma2(pb, wv.x, acc[1][2 * j + 0]);
        acc[1][2 * j + 1] = fma2(pb, wv.y, acc[1][2 * j + 1]);
    }
}

template <int COT, int RELU>
__global__ void __launch_bounds__(128) convt2_k(
    const float* __restrict__ in1, const float* __restrict__ in2,
    const float* __restrict__ w, const float* __restrict__ bias,
    float* __restrict__ y, int N, int Ci1, int Ci2, int Hi, int Wi, int Co)
{
    const int Ho = Hi * 2, Wo = Wi * 2;
    __shared__ float sx[8][6][19];
    __shared__ __align__(16) float sw[8 * 16 * COT];

    const int tid = threadIdx.x;
    const int tx = tid & 15, ty = tid >> 4;
    const int cogs = (Co + COT - 1) / COT;
    const int n = blockIdx.z / cogs, cog = blockIdx.z % cogs;
    const int ho = blockIdx.y * 8 + ty;
    const int wo1 = blockIdx.x * 32 + tx;
    const int hi_base = blockIdx.y * 4 - 1;
    const int wi_base = blockIdx.x * 16 - 1;
    const int Ci = Ci1 + Ci2;

    // staging roles (divmod-free)
    const int scc = tid & 15;       // column 0..15
    const int sg = tid >> 4;        // group 0..7
    const int swi = wi_base + scc;
    const bool swok = (swi >= 0) && (swi < Wi);

    const int ph = (ty + 1) & 1, pw = (tx + 1) & 1;
    const int ha = ((ty + 1 - ph) >> 1) + 1, hb = ha - 1;
    const int wa = ((tx + 1 - pw) >> 1) + 1, wb = wa - 1;
    const int k1 = ph * 4 + pw, k2 = k1 + 2, k3 = k1 + 8, k4 = k1 + 10;

    ull acc[2][COT / 2];
#pragma unroll
    for (int p = 0; p < 2; ++p)
#pragma unroll
        for (int j = 0; j < COT / 2; ++j) acc[p][j] = 0ULL;

    for (int ci0 = 0; ci0 < Ci; ci0 += 8) {
        __syncthreads();
        // ---- input staging: main 16 columns, 6 iters x 8 (c,r) pairs ----
#pragma unroll
        for (int it = 0; it < 6; ++it) {
            const int p = it * 8 + sg;      // 0..47
            const int r = p >> 3, c = p & 7;
            const int ci = ci0 + c;
            const int hi = hi_base + r;
            float v = 0.f;
            if (swok && hi >= 0 && hi < Hi) {
                const float* xp = (ci < Ci1)
                    ? in1 + (size_t)(n * Ci1 + ci) * Hi * Wi
                    : in2 + (size_t)(n * Ci2 + (ci - Ci1)) * Hi * Wi;
                v = xp[(size_t)hi * Wi + swi];
            }
            sx[c][r][scc] = v;
        }
        // ---- input staging: columns 16,17 (96 elements, pow2 decode) ----
        if (tid < 96) {
            const int cc = 16 + (tid & 1);
            const int p = tid >> 1;         // 0..47
            const int r = p >> 3, c = p & 7;
            const int ci = ci0 + c;
            const int hi = hi_base + r, wi = wi_base + cc;
            float v = 0.f;
            if (hi >= 0 && hi < Hi && wi >= 0 && wi < Wi) {
                const float* xp = (ci < Ci1)
                    ? in1 + (size_t)(n * Ci1 + ci) * Hi * Wi
                    : in2 + (size_t)(n * Ci2 + (ci - Ci1)) * Hi * Wi;
                v = xp[(size_t)hi * Wi + wi];
            }
            sx[c][r][cc] = v;
        }
        // ---- weight staging (pow2 divisors -> free) ----
        for (int idx = tid; idx < 8 * 16 * COT; idx += 128) {
            int c = idx / (16 * COT), rem = idx % (16 * COT);
            int k = rem / COT, co = rem % COT;
            int ci = ci0 + c, cg = cog * COT + co;
            sw[idx] = (cg < Co) ? w[((size_t)ci * Co + cg) * 16 + k] : 0.f;
        }
        __syncthreads();
#pragma unroll
        for (int c = 0; c < 8; ++c) {
            float x1aa = sx[c][ha][wa],     x1ab = sx[c][ha][wb];
            float x1ba = sx[c][hb][wa],     x1bb = sx[c][hb][wb];
            float x2aa = sx[c][ha][wa + 8], x2ab = sx[c][ha][wb + 8];
            float x2ba = sx[c][hb][wa + 8], x2bb = sx[c][hb][wb + 8];
            const float* wb0 = &sw[c * 16 * COT];
            ct_tap2<COT>(acc, wb0 + k1 * COT, x1aa, x2aa);
            ct_tap2<COT>(acc, wb0 + k2 * COT, x1ab, x2ab);
            ct_tap2<COT>(acc, wb0 + k3 * COT, x1ba, x2ba);
            ct_tap2<COT>(acc, wb0 + k4 * COT, x1bb, x2bb);
        }
    }
#pragma unroll
    for (int p = 0; p < 2; ++p) {
        int wo = wo1 + p * 16;
#pragma unroll
        for (int j = 0; j < COT / 2; ++j) {
            float v0, v1;
            unpack2(acc[p][j], v0, v1);
            int cg0 = cog * COT + 2 * j;
            if (cg0 < Co) {
                float r0 = v0 + bias[cg0];
                if (RELU) r0 = fmaxf(r0, 0.f);
                y[((size_t)(n * Co + cg0) * Ho + ho) * Wo + wo] = r0;
            }
            if (cg0 + 1 < Co) {
                float r1 = v1 + bias[cg0 + 1];
                if (RELU) r1 = fmaxf(r1, 0.f);
                y[((size_t)(n * Co + cg0 + 1) * Ho + ho) * Wo + wo] = r1;
            }
        }
    }
}

// ---------------------------------------------------------------------------
__global__ void loss_k(float* __restrict__ out) {
    out[0] = g_sum_t[0] * (1.f / (16384.f * 64.f)) + g_sum_b[0] * (1.f / (65536.f * 64.f));
}

// ---------------------------------------------------------------------------
static float* symf(const void* s) {
    void* p = nullptr;
    cudaGetSymbolAddress(&p, s);
    return (float*)p;
}

extern "C" void kernel_launch(void* const* d_in, const int* in_sizes, int n_in,
                              void* d_out, int out_size) {
    (void)in_sizes; (void)n_in; (void)out_size;
    const float* x       = (const float*)d_in[0];
    const float* wb1     = (const float*)d_in[1];
    const float* bb1     = (const float*)d_in[2];
    const float* wb2     = (const float*)d_in[3];
    const float* bb2     = (const float*)d_in[4];
    const float* wt1     = (const float*)d_in[5];
    const float* bt1     = (const float*)d_in[6];
    const float* wqt     = (const float*)d_in[7];
    const float* bqt     = (const float*)d_in[8];
    const float* embed_t = (const float*)d_in[9];
    const float* wdt     = (const float*)d_in[10];
    const float* bdt     = (const float*)d_in[11];
    const float* wqb     = (const float*)d_in[12];
    const float* bqb     = (const float*)d_in[13];
    const float* embed_b = (const float*)d_in[14];
    const float* wup     = (const float*)d_in[15];
    const float* bup     = (const float*)d_in[16];
    const float* wd1     = (const float*)d_in[17];
    const float* bd1     = (const float*)d_in[18];
    const float* wd2     = (const float*)d_in[19];
    const float* bd2     = (const float*)d_in[20];

    float* out = (float*)d_out;
    float* o_xhat = out;
    float* o_qt   = out + 3145728;
    float* o_qb   = out + 3145728 + 1048576;
    float* o_loss = out + 8388608;
    float* o_idt  = out + 8388609;
    float* o_idb  = out + 8388609 + 16384;

    float* enc_b1 = symf(g_enc_b1);
    float* enc_b  = symf(g_enc_b);
    float* enc_t  = symf(g_enc_t);
    float* qt     = symf(g_qt);
    float* dec_t  = symf(g_dec_t);
    float* qb     = symf(g_qb);
    float* up_t   = symf(g_up_t);
    float* h      = symf(g_h);
    float* e2t    = symf(g_e2t);
    float* e2b    = symf(g_e2b);
    float* sum_t  = symf(g_sum_t);
    float* sum_b  = symf(g_sum_b);

    prep_kernel<<<2, 512>>>(embed_t, embed_b);

    // encoder (R11 grids)
    conv_down2_k<32, 1><<<dim3(8, 8, 64), 128>>>(x,      wb1, bb1, enc_b1, 16,   3, 256, 256, 128);
    conv_down2_k<16, 1><<<dim3(4, 4, 128), 128>>>(enc_b1, wb2, bb2, enc_b,  16, 128, 128, 128, 128);
    conv_down2_k<16, 1><<<dim3(2, 2, 128), 128>>>(enc_b,  wt1, bt1, enc_t,  16, 128,  64,  64, 128);

    // top quantize
    conv1x1_nhwc_k<<<128, 128>>>(enc_t, nullptr, wqt, bqt, qt, 128, 0, 1024);
    quantize_k<<<1024, 128>>>(qt, embed_t, e2t, o_qt, o_idt, sum_t, 1024);

    // decoder_top + bottom quantize
    convt2_k<16, 0><<<dim3(2, 8, 64), 128>>>(o_qt, nullptr, wdt, bdt, dec_t, 16, 64, 0, 32, 32, 64);
    conv1x1_nhwc_k<<<512, 128>>>(dec_t, enc_b, wqb, bqb, qb, 64, 128, 4096);
    quantize_k<<<4096, 128>>>(qb, embed_b, e2b, o_qb, o_idb, sum_b, 4096);

    // decode (R11 grids)
    convt2_k<16, 0><<<dim3(2, 8, 64), 128>>>(o_qt, nullptr, wup, bup, up_t, 16, 64, 0, 32, 32, 64);
    convt2_k<16, 1><<<dim3(4, 16, 64), 128>>>(up_t, o_qb,   wd1, bd1, h,    16, 64, 64, 64, 64, 64);
    convt2_k<4,  0><<<dim3(8, 32, 16), 128>>>(h,   nullptr, wd2, bd2, o_xhat, 16, 64, 0, 128, 128, 3);

    loss_k<<<1, 1>>>(o_loss);
}